// round 5
// baseline (speedup 1.0000x reference)
#include <cuda_runtime.h>
#include <cuda_bf16.h>
#include <cstdint>

// Decoder (Conv-TasNet): out = overlap_add( (mixture_w * est_mask)^T @ W^T, step=L/2 )
// mixture_w/est_mask [B, N, K] f32, W [L, N] f32, out [B, T] f32
// B=4, N=512, K=16000, L=16, step=8, T = 8*(K-1)+16 = 128008
//
// Design: one block per (b, 128-frame k-tile). The block consumes ALL N=512
// channels (no N-split -> no redundant atomics). Inputs stream through a
// 4-stage cp.async shared-memory pipeline (MLP decoupled from registers).
// Overlap-add is resolved in shared memory; only the 8-float halos at tile
// edges use atomicAdd.

#define DEC_B 4
#define DEC_N 512
#define DEC_K 16000
#define DEC_L 16
#define DEC_STEP 8
#define DEC_T (DEC_STEP * (DEC_K - 1) + DEC_L)   // 128008

#define TPB 128
#define KT  128                       // frames per block (== TPB, 1 frame/thread)
#define SN  8                         // n-rows per pipeline stage
#define S   4                         // pipeline stages
#define NSTG (DEC_N / SN)             // 64 stage-iterations

// shared-memory layout (floats)
#define OFF_W  0
#define OFF_M  (DEC_N * DEC_L)                     // 8192
#define OFF_E  (OFF_M + S * SN * KT)               // +4096 = 12288
#define OFF_OB (OFF_E + S * SN * KT)               // +4096 = 16384
#define OB_LEN (KT * DEC_STEP + DEC_STEP)          // 1032
#define SMEM_FLOATS (OFF_OB + OB_LEN)              // 17416
#define SMEM_BYTES  (SMEM_FLOATS * 4)              // 69664 B -> 3 blocks/SM

__device__ __forceinline__ void cp_async16(uint32_t dst, const void* src) {
    asm volatile("cp.async.cg.shared.global [%0], [%1], 16;\n"
                 :: "r"(dst), "l"(src) : "memory");
}
__device__ __forceinline__ void cp_commit() {
    asm volatile("cp.async.commit_group;\n" ::: "memory");
}
__device__ __forceinline__ void cp_wait2() {
    asm volatile("cp.async.wait_group %0;\n" :: "n"(S - 2) : "memory");
}

__global__ __launch_bounds__(TPB)
void decoder_kernel(const float* __restrict__ mw,
                    const float* __restrict__ em,
                    const float* __restrict__ W,
                    float* __restrict__ out)
{
    extern __shared__ float smem[];
    float* Ws = smem + OFF_W;   // [512][16] transposed W
    float* sm = smem + OFF_M;   // [S][SN][KT] mixture_w stage buffers
    float* se = smem + OFF_E;   // [S][SN][KT] est_mask stage buffers
    float* ob = smem + OFF_OB;  // [1032] overlap-add buffer

    const int tid = threadIdx.x;
    const int b   = blockIdx.y;
    const int k0  = blockIdx.x * KT;

    const float* __restrict__ mwb = mw + (size_t)b * DEC_N * DEC_K + k0;
    const float* __restrict__ emb = em + (size_t)b * DEC_N * DEC_K + k0;

    // Issue one stage: SN rows x 512B of mw and em -> 512 x 16B cp.async ops,
    // 4 per thread. opidx -> {array, row, 16B-offset}.
    auto issue_stage = [&](int st) {
        int buf = st & (S - 1);
        float* dm = sm + buf * (SN * KT);
        float* de = se + buf * (SN * KT);
        int nbase = st * SN;
#pragma unroll
        for (int i = 0; i < 4; ++i) {
            int opidx = tid + i * TPB;          // 0..511
            int arr   = opidx >> 8;             // 0 = mw, 1 = em
            int rem   = opidx & 255;
            int row   = rem >> 5;               // 0..7
            int off   = (rem & 31) * 4;         // float offset, 16B granularity
            const float* src = (arr ? emb : mwb) + (size_t)(nbase + row) * DEC_K + off;
            float* dst = (arr ? de : dm) + row * KT + off;
            cp_async16((uint32_t)__cvta_generic_to_shared(dst), src);
        }
        cp_commit();
    };

    // Prologue: stages 0..S-2 in flight before any compute.
    for (int st = 0; st < S - 1; ++st) issue_stage(st);

    // Transpose W into smem (coalesced global reads; consumed after first sync).
#pragma unroll
    for (int j = 0; j < (DEC_N * DEC_L) / TPB; ++j) {
        int i = tid + j * TPB;      // i = l*512 + n
        float w = W[i];
        int l = i >> 9;
        int n = i & 511;
        Ws[n * DEC_L + l] = w;
    }

    float acc[DEC_L];
#pragma unroll
    for (int l = 0; l < DEC_L; ++l) acc[l] = 0.0f;

    for (int s = 0; s < NSTG; ++s) {
        cp_wait2();            // stage s complete (<= S-2 groups pending)
        __syncthreads();       // make stage s visible block-wide; fences buffer reuse

        int buf = s & (S - 1);
        const float* cm = sm + buf * (SN * KT) + tid;
        const float* ce = se + buf * (SN * KT) + tid;
        const float* wr = Ws + s * SN * DEC_L;

#pragma unroll
        for (int r = 0; r < SN; ++r) {
            float p = cm[r * KT] * ce[r * KT];
            const float4* w4 = reinterpret_cast<const float4*>(wr + r * DEC_L);
            float4 w0 = w4[0];
            float4 w1 = w4[1];
            float4 w2 = w4[2];
            float4 w3 = w4[3];
            acc[0]  = fmaf(p, w0.x, acc[0]);
            acc[1]  = fmaf(p, w0.y, acc[1]);
            acc[2]  = fmaf(p, w0.z, acc[2]);
            acc[3]  = fmaf(p, w0.w, acc[3]);
            acc[4]  = fmaf(p, w1.x, acc[4]);
            acc[5]  = fmaf(p, w1.y, acc[5]);
            acc[6]  = fmaf(p, w1.z, acc[6]);
            acc[7]  = fmaf(p, w1.w, acc[7]);
            acc[8]  = fmaf(p, w2.x, acc[8]);
            acc[9]  = fmaf(p, w2.y, acc[9]);
            acc[10] = fmaf(p, w2.z, acc[10]);
            acc[11] = fmaf(p, w2.w, acc[11]);
            acc[12] = fmaf(p, w3.x, acc[12]);
            acc[13] = fmaf(p, w3.y, acc[13]);
            acc[14] = fmaf(p, w3.z, acc[14]);
            acc[15] = fmaf(p, w3.w, acc[15]);
        }

        if (s + S - 1 < NSTG) issue_stage(s + S - 1);
        else                  cp_commit();     // keep group accounting aligned
    }

    // ---- overlap-add in shared memory ----
    __syncthreads();
    float* obt = ob + tid * DEC_STEP;
    // phase 1: exclusive low halves; zero the 8-float tail slot
#pragma unroll
    for (int l = 0; l < DEC_STEP; ++l) obt[l] = acc[l];
    if (tid < DEC_STEP) ob[KT * DEC_STEP + tid] = 0.0f;
    __syncthreads();
    // phase 2: add high halves into the neighbor's slot (exclusive per thread)
#pragma unroll
    for (int l = 0; l < DEC_STEP; ++l) obt[DEC_STEP + l] += acc[DEC_STEP + l];
    __syncthreads();
    // phase 3: write out. Interior is exclusive to this block (plain stores);
    // only the 8-float halos at each end can collide with neighbor tiles.
    float* __restrict__ op = out + (size_t)b * DEC_T + (size_t)k0 * DEC_STEP;
    for (int j = tid; j < OB_LEN; j += TPB) {
        float v = ob[j];
        if (j < DEC_STEP || j >= KT * DEC_STEP) atomicAdd(&op[j], v);
        else                                    op[j] = v;
    }
}

extern "C" void kernel_launch(void* const* d_in, const int* in_sizes, int n_in,
                              void* d_out, int out_size)
{
    const float* mixture_w = (const float*)d_in[0];  // [B, N, K]
    const float* est_mask  = (const float*)d_in[1];  // [B, N, K]
    const float* W         = (const float*)d_in[2];  // [L, N]
    float* out = (float*)d_out;                       // [B, T]

    cudaFuncSetAttribute(decoder_kernel,
                         cudaFuncAttributeMaxDynamicSharedMemorySize, SMEM_BYTES);

    // Zero output (only the halo floats strictly need it, full memset is cheap).
    cudaMemsetAsync(out, 0, (size_t)out_size * sizeof(float), 0);

    dim3 grid(DEC_K / KT, DEC_B);   // (125, 4)
    decoder_kernel<<<grid, TPB, SMEM_BYTES>>>(mixture_w, est_mask, W, out);
}

// round 6
// speedup vs baseline: 1.2697x; 1.2697x over previous
#include <cuda_runtime.h>
#include <cuda_bf16.h>
#include <cstdint>

// Decoder (Conv-TasNet): out = overlap_add( (mixture_w * est_mask)^T @ W^T, step=L/2 )
// mixture_w/est_mask [B, N, K] f32, W [L, N] f32, out [B, T] f32
// B=4, N=512, K=16000, L=16, step=8, T = 8*(K-1)+16 = 128008
//
// R6 design: KPT=1 (16 accs as 8 packed f32x2), TPB=256, NSPLIT=4.
// Explicit 8-deep load batches give each warp 16 independent LDG.32 in flight;
// fma.rn.f32x2 halves FMA issue pressure (removes the scalar-FFMA floor).

#define DEC_B 4
#define DEC_N 512
#define DEC_K 16000
#define DEC_L 16
#define DEC_STEP 8
#define DEC_T (DEC_STEP * (DEC_K - 1) + DEC_L)   // 128008

#define TPB 256
#define NSPLIT 4
#define NCHUNK (DEC_N / NSPLIT)      // 128
#define NB 8                          // n's per load batch

#define FMA_F32X2(d, a, b, c) \
    asm("fma.rn.f32x2 %0, %1, %2, %3;" \
        : "=l"(d) : "l"(a), "l"(b), "l"(c))

__global__ __launch_bounds__(TPB, 4)
void decoder_kernel(const float* __restrict__ mw,
                    const float* __restrict__ em,
                    const float* __restrict__ W,
                    float* __restrict__ out)
{
    // Stage this block's N-chunk of W transposed: Ws[n_local][l], 8 KB.
    __shared__ float Ws[NCHUNK * DEC_L];
    const int nb = blockIdx.z * NCHUNK;
    for (int i = threadIdx.x; i < NCHUNK * DEC_L; i += TPB) {
        int n = i >> 4;
        int l = i & 15;
        Ws[i] = W[l * DEC_N + nb + n];
    }
    __syncthreads();

    const int b = blockIdx.y;
    const int k = blockIdx.x * TPB + threadIdx.x;
    if (k >= DEC_K) return;   // tail block: inactive threads exit after staging

    const float* __restrict__ mwp = mw + (size_t)b * DEC_N * DEC_K
                                       + (size_t)nb * DEC_K + k;
    const float* __restrict__ emp = em + (size_t)b * DEC_N * DEC_K
                                       + (size_t)nb * DEC_K + k;

    // 16 fp32 accumulators packed as 8 x f32x2.
    unsigned long long accp[8];
#pragma unroll
    for (int i = 0; i < 8; ++i) accp[i] = 0ull;

    for (int n0 = 0; n0 < NCHUNK; n0 += NB) {
        // Batch phase: 16 independent coalesced streaming LDG.32s.
        float m[NB], e[NB];
#pragma unroll
        for (int j = 0; j < NB; ++j) {
            m[j] = __ldcs(&mwp[(size_t)(n0 + j) * DEC_K]);
            e[j] = __ldcs(&emp[(size_t)(n0 + j) * DEC_K]);
        }
        // Compute phase: per n, 1 mul + 1 pack + 8 FFMA2 (all lanes same n ->
        // Ws reads are warp-broadcast LDS.64, conflict-free).
#pragma unroll
        for (int j = 0; j < NB; ++j) {
            float p = m[j] * e[j];
            unsigned long long pp;
            asm("mov.b64 %0, {%1, %1};" : "=l"(pp) : "f"(p));
            const unsigned long long* w2 =
                reinterpret_cast<const unsigned long long*>(&Ws[(n0 + j) * DEC_L]);
#pragma unroll
            for (int i = 0; i < 8; ++i) {
                FMA_F32X2(accp[i], w2[i], pp, accp[i]);
            }
        }
    }

    // Overlap-add: frame k covers out[b, 8k .. 8k+15]; <= 2*NSPLIT = 8 fp32
    // contributions per output element (atomicAdd, order-insensitive result
    // structure identical to the passing R2 kernel).
    float* __restrict__ op = out + (size_t)b * DEC_T + (size_t)k * DEC_STEP;
#pragma unroll
    for (int i = 0; i < 8; ++i) {
        float2 v;
        asm("mov.b64 {%0, %1}, %2;" : "=f"(v.x), "=f"(v.y) : "l"(accp[i]));
        atomicAdd(&op[2 * i],     v.x);
        atomicAdd(&op[2 * i + 1], v.y);
    }
}

extern "C" void kernel_launch(void* const* d_in, const int* in_sizes, int n_in,
                              void* d_out, int out_size)
{
    const float* mixture_w = (const float*)d_in[0];  // [B, N, K]
    const float* est_mask  = (const float*)d_in[1];  // [B, N, K]
    const float* W         = (const float*)d_in[2];  // [L, N]
    float* out = (float*)d_out;                       // [B, T]

    cudaMemsetAsync(out, 0, (size_t)out_size * sizeof(float), 0);

    dim3 grid((DEC_K + TPB - 1) / TPB, DEC_B, NSPLIT);  // (63, 4, 4)
    decoder_kernel<<<grid, TPB>>>(mixture_w, est_mask, W, out);
}

// round 7
// speedup vs baseline: 1.4771x; 1.1634x over previous
#include <cuda_runtime.h>
#include <cuda_bf16.h>
#include <cstdint>

// Decoder (Conv-TasNet): out = overlap_add( (mixture_w * est_mask)^T @ W^T, step=L/2 )
// mixture_w/est_mask [B, N, K] f32, W [L, N] f32, out [B, T] f32
// B=4, N=512, K=16000, L=16, step=8, T = 8*(K-1)+16 = 128008
//
// R7: instruction-count-optimized. KPT=2 (LDG.64 amortized over 2 frames) +
// fully packed f32x2 math (mul + 16 FFMA2 per n) + LDS.128 W reads.
// ~13 instrs per (k, n) vs 20-28 in prior rounds; issue time drops below the
// DRAM stream floor so the kernel finally becomes bandwidth-bound.

#define DEC_B 4
#define DEC_N 512
#define DEC_K 16000
#define DEC_L 16
#define DEC_STEP 8
#define DEC_T (DEC_STEP * (DEC_K - 1) + DEC_L)   // 128008

#define TPB 128
#define NSPLIT 4
#define NCHUNK (DEC_N / NSPLIT)      // 128
#define KPT 2                         // frames per thread (float2/b64 along k)
#define NB 4                          // n's per load batch (8 LDG.64 in flight)
#define NACC 12                       // f32x2 accumulators (24 out positions)

typedef unsigned long long u64t;

#define FMA_F32X2(d, a, b, c) \
    asm("fma.rn.f32x2 %0, %1, %2, %3;" : "=l"(d) : "l"(a), "l"(b), "l"(c))
#define MUL_F32X2_(d, a, b) \
    asm("mul.rn.f32x2 %0, %1, %2;" : "=l"(d) : "l"(a), "l"(b))

__global__ __launch_bounds__(TPB)
void decoder_kernel(const float* __restrict__ mw,
                    const float* __restrict__ em,
                    const float* __restrict__ W,
                    float* __restrict__ out)
{
    // Stage this block's N-chunk of W transposed: Ws[n_local][l], 8 KB.
    __shared__ float Ws[NCHUNK * DEC_L];
    const int nb = blockIdx.z * NCHUNK;
    for (int i = threadIdx.x; i < NCHUNK * DEC_L; i += TPB) {
        int n = i >> 4;
        int l = i & 15;
        Ws[i] = W[l * DEC_N + nb + n];
    }
    __syncthreads();

    const int b  = blockIdx.y;
    const int k0 = (blockIdx.x * TPB + threadIdx.x) * KPT;
    if (k0 >= DEC_K) return;   // tail guard (grid.x*TPB*KPT = 16128 > 16000)

    const size_t base = (size_t)b * DEC_N * DEC_K + (size_t)nb * DEC_K + k0;
    const u64t* __restrict__ mwp = reinterpret_cast<const u64t*>(mw + base);
    const u64t* __restrict__ emp = reinterpret_cast<const u64t*>(em + base);
    const size_t kstr = DEC_K / 2;   // b64 stride between n rows

    // 24 fp32 accumulators as 12 x f32x2. Frame k0 -> accp[0..7],
    // frame k0+1 -> accp[4..11] (offset 8 positions = 4 pairs, pair-aligned).
    u64t accp[NACC];
#pragma unroll
    for (int i = 0; i < NACC; ++i) accp[i] = 0ull;

    for (int n0 = 0; n0 < NCHUNK; n0 += NB) {
        // Batch: 8 independent coalesced streaming LDG.64s (16 lines in flight).
        u64t m[NB], e[NB];
#pragma unroll
        for (int j = 0; j < NB; ++j) {
            m[j] = __ldcs(&mwp[(size_t)(n0 + j) * kstr]);
            e[j] = __ldcs(&emp[(size_t)(n0 + j) * kstr]);
        }
#pragma unroll
        for (int j = 0; j < NB; ++j) {
            // (p0, p1) in one packed multiply
            u64t pq;
            MUL_F32X2_(pq, m[j], e[j]);
            float p0, p1;
            asm("mov.b64 {%0, %1}, %2;" : "=f"(p0), "=f"(p1) : "l"(pq));
            u64t pp0, pp1;
            asm("mov.b64 %0, {%1, %1};" : "=l"(pp0) : "f"(p0));
            asm("mov.b64 %0, {%1, %1};" : "=l"(pp1) : "f"(p1));

            // 4x LDS.128 (warp-broadcast) -> 8 w-pairs
            const float4* w4 = reinterpret_cast<const float4*>(&Ws[(n0 + j) * DEC_L]);
            float4 wa = w4[0];
            float4 wb = w4[1];
            float4 wc = w4[2];
            float4 wd = w4[3];
            u64t w01, w23, w45, w67, w89, wAB, wCD, wEF;
            asm("mov.b64 %0, {%1, %2};" : "=l"(w01) : "f"(wa.x), "f"(wa.y));
            asm("mov.b64 %0, {%1, %2};" : "=l"(w23) : "f"(wa.z), "f"(wa.w));
            asm("mov.b64 %0, {%1, %2};" : "=l"(w45) : "f"(wb.x), "f"(wb.y));
            asm("mov.b64 %0, {%1, %2};" : "=l"(w67) : "f"(wb.z), "f"(wb.w));
            asm("mov.b64 %0, {%1, %2};" : "=l"(w89) : "f"(wc.x), "f"(wc.y));
            asm("mov.b64 %0, {%1, %2};" : "=l"(wAB) : "f"(wc.z), "f"(wc.w));
            asm("mov.b64 %0, {%1, %2};" : "=l"(wCD) : "f"(wd.x), "f"(wd.y));
            asm("mov.b64 %0, {%1, %2};" : "=l"(wEF) : "f"(wd.z), "f"(wd.w));

            // frame 0: positions 0..15
            FMA_F32X2(accp[0],  w01, pp0, accp[0]);
            FMA_F32X2(accp[1],  w23, pp0, accp[1]);
            FMA_F32X2(accp[2],  w45, pp0, accp[2]);
            FMA_F32X2(accp[3],  w67, pp0, accp[3]);
            FMA_F32X2(accp[4],  w89, pp0, accp[4]);
            FMA_F32X2(accp[5],  wAB, pp0, accp[5]);
            FMA_F32X2(accp[6],  wCD, pp0, accp[6]);
            FMA_F32X2(accp[7],  wEF, pp0, accp[7]);
            // frame 1: positions 8..23
            FMA_F32X2(accp[4],  w01, pp1, accp[4]);
            FMA_F32X2(accp[5],  w23, pp1, accp[5]);
            FMA_F32X2(accp[6],  w45, pp1, accp[6]);
            FMA_F32X2(accp[7],  w67, pp1, accp[7]);
            FMA_F32X2(accp[8],  w89, pp1, accp[8]);
            FMA_F32X2(accp[9],  wAB, pp1, accp[9]);
            FMA_F32X2(accp[10], wCD, pp1, accp[10]);
            FMA_F32X2(accp[11], wEF, pp1, accp[11]);
        }
    }

    // Scatter-add 24 unique positions (frames k0, k0+1). Each out element
    // receives <= 2*NSPLIT = 8 fp32 contributions (atomic, order-insensitive
    // structure identical to the passing R2 kernel).
    float* __restrict__ op = out + (size_t)b * DEC_T + (size_t)k0 * DEC_STEP;
#pragma unroll
    for (int i = 0; i < NACC; ++i) {
        float lo, hi;
        asm("mov.b64 {%0, %1}, %2;" : "=f"(lo), "=f"(hi) : "l"(accp[i]));
        atomicAdd(&op[2 * i],     lo);
        atomicAdd(&op[2 * i + 1], hi);
    }
}

extern "C" void kernel_launch(void* const* d_in, const int* in_sizes, int n_in,
                              void* d_out, int out_size)
{
    const float* mixture_w = (const float*)d_in[0];  // [B, N, K]
    const float* est_mask  = (const float*)d_in[1];  // [B, N, K]
    const float* W         = (const float*)d_in[2];  // [L, N]
    float* out = (float*)d_out;                       // [B, T]

    cudaMemsetAsync(out, 0, (size_t)out_size * sizeof(float), 0);

    dim3 grid((DEC_K + TPB * KPT - 1) / (TPB * KPT), DEC_B, NSPLIT);  // (63, 4, 4)
    decoder_kernel<<<grid, TPB>>>(mixture_w, est_mask, W, out);
}

// round 8
// speedup vs baseline: 1.4779x; 1.0005x over previous
#include <cuda_runtime.h>
#include <cuda_bf16.h>
#include <cstdint>

// Decoder (Conv-TasNet): out = overlap_add( (mixture_w * est_mask)^T @ W^T, step=L/2 )
// mixture_w/est_mask [B, N, K] f32, W [L, N] f32, out [B, T] f32
// B=4, N=512, K=16000, L=16, step=8, T = 8*(K-1)+16 = 128008
//
// R8: R7 minus the mov.b64 repacks (W read as ulonglong2 -> u64 pairs direct
// from LDS.128), plus an explicit A/B double-buffered load pipeline so the
// next batch's 8 LDG.64s are in flight during the current compute phase.

#define DEC_B 4
#define DEC_N 512
#define DEC_K 16000
#define DEC_L 16
#define DEC_STEP 8
#define DEC_T (DEC_STEP * (DEC_K - 1) + DEC_L)   // 128008

#define TPB 128
#define NSPLIT 4
#define NCHUNK (DEC_N / NSPLIT)      // 128
#define KPT 2                         // frames per thread (float2 along k)
#define NB 4                          // n's per load batch (8 LDG.64 in flight)
#define NACC 12                       // f32x2 accumulators (24 out positions)

typedef unsigned long long u64t;

#define FMA_F32X2(d, a, b, c) \
    asm("fma.rn.f32x2 %0, %1, %2, %3;" : "=l"(d) : "l"(a), "l"(b), "l"(c))

__global__ __launch_bounds__(TPB)
void decoder_kernel(const float* __restrict__ mw,
                    const float* __restrict__ em,
                    const float* __restrict__ W,
                    float* __restrict__ out)
{
    // This block's N-chunk of W, transposed: Ws[n_local][l]. 8 KB, 16B-aligned
    // so each row is 4x LDS.128.
    __shared__ __align__(16) float Ws[NCHUNK * DEC_L];
    const int nb = blockIdx.z * NCHUNK;
    for (int i = threadIdx.x; i < NCHUNK * DEC_L; i += TPB) {
        int n = i >> 4;
        int l = i & 15;
        Ws[i] = W[l * DEC_N + nb + n];
    }
    __syncthreads();

    const int b  = blockIdx.y;
    const int k0 = (blockIdx.x * TPB + threadIdx.x) * KPT;
    if (k0 >= DEC_K) return;   // tail guard (63*128*2 = 16128 > 16000)

    const size_t base = (size_t)b * DEC_N * DEC_K + (size_t)nb * DEC_K + k0;
    const float2* __restrict__ mwp = reinterpret_cast<const float2*>(mw + base);
    const float2* __restrict__ emp = reinterpret_cast<const float2*>(em + base);
    const size_t kstr = DEC_K / 2;   // float2 stride between n rows

    // 24 fp32 accumulators as 12 x f32x2. Frame k0 -> accp[0..7],
    // frame k0+1 -> accp[4..11] (overlap of 8 positions = 4 pairs).
    u64t accp[NACC];
#pragma unroll
    for (int i = 0; i < NACC; ++i) accp[i] = 0ull;

    // One n-step: 2 FMUL + 2 packs + 4 LDS.128 + 16 FFMA2 (no repack movs).
    auto step = [&](int n, float2 m, float2 e) {
        float p0 = m.x * e.x;
        float p1 = m.y * e.y;
        u64t pp0, pp1;
        asm("mov.b64 %0, {%1, %1};" : "=l"(pp0) : "f"(p0));
        asm("mov.b64 %0, {%1, %1};" : "=l"(pp1) : "f"(p1));

        const ulonglong2* w = reinterpret_cast<const ulonglong2*>(&Ws[n * DEC_L]);
        ulonglong2 w0 = w[0];   // pairs (l0,l1) (l2,l3)
        ulonglong2 w1 = w[1];   // pairs (l4,l5) (l6,l7)
        ulonglong2 w2 = w[2];   // pairs (l8,l9) (l10,l11)
        ulonglong2 w3 = w[3];   // pairs (l12,l13) (l14,l15)

        // frame 0: out positions 0..15
        FMA_F32X2(accp[0],  w0.x, pp0, accp[0]);
        FMA_F32X2(accp[1],  w0.y, pp0, accp[1]);
        FMA_F32X2(accp[2],  w1.x, pp0, accp[2]);
        FMA_F32X2(accp[3],  w1.y, pp0, accp[3]);
        FMA_F32X2(accp[4],  w2.x, pp0, accp[4]);
        FMA_F32X2(accp[5],  w2.y, pp0, accp[5]);
        FMA_F32X2(accp[6],  w3.x, pp0, accp[6]);
        FMA_F32X2(accp[7],  w3.y, pp0, accp[7]);
        // frame 1: out positions 8..23
        FMA_F32X2(accp[4],  w0.x, pp1, accp[4]);
        FMA_F32X2(accp[5],  w0.y, pp1, accp[5]);
        FMA_F32X2(accp[6],  w1.x, pp1, accp[6]);
        FMA_F32X2(accp[7],  w1.y, pp1, accp[7]);
        FMA_F32X2(accp[8],  w2.x, pp1, accp[8]);
        FMA_F32X2(accp[9],  w2.y, pp1, accp[9]);
        FMA_F32X2(accp[10], w3.x, pp1, accp[10]);
        FMA_F32X2(accp[11], w3.y, pp1, accp[11]);
    };

    // A/B double-buffered batches: 8 LDG.64 for batch t+1 in flight while
    // computing batch t.
    float2 mA[NB], eA[NB], mB[NB], eB[NB];
#pragma unroll
    for (int j = 0; j < NB; ++j) {
        mA[j] = __ldcs(&mwp[(size_t)j * kstr]);
        eA[j] = __ldcs(&emp[(size_t)j * kstr]);
    }

#pragma unroll 1
    for (int n0 = 0; n0 < NCHUNK; n0 += 2 * NB) {
        // prefetch B = n0+NB .. n0+2NB-1
#pragma unroll
        for (int j = 0; j < NB; ++j) {
            mB[j] = __ldcs(&mwp[(size_t)(n0 + NB + j) * kstr]);
            eB[j] = __ldcs(&emp[(size_t)(n0 + NB + j) * kstr]);
        }
        // compute A
#pragma unroll
        for (int j = 0; j < NB; ++j) step(n0 + j, mA[j], eA[j]);

        // prefetch A = n0+2NB .. (NCHUNK % (2*NB) == 0 so no OOB)
        if (n0 + 2 * NB < NCHUNK) {
#pragma unroll
            for (int j = 0; j < NB; ++j) {
                mA[j] = __ldcs(&mwp[(size_t)(n0 + 2 * NB + j) * kstr]);
                eA[j] = __ldcs(&emp[(size_t)(n0 + 2 * NB + j) * kstr]);
            }
        }
        // compute B
#pragma unroll
        for (int j = 0; j < NB; ++j) step(n0 + NB + j, mB[j], eB[j]);
    }

    // Scatter-add 24 unique positions (frames k0, k0+1). <= 2*NSPLIT = 8 fp32
    // contributions per output element (atomic, order-insensitive).
    float* __restrict__ op = out + (size_t)b * DEC_T + (size_t)k0 * DEC_STEP;
#pragma unroll
    for (int i = 0; i < NACC; ++i) {
        float lo, hi;
        asm("mov.b64 {%0, %1}, %2;" : "=f"(lo), "=f"(hi) : "l"(accp[i]));
        atomicAdd(&op[2 * i],     lo);
        atomicAdd(&op[2 * i + 1], hi);
    }
}

extern "C" void kernel_launch(void* const* d_in, const int* in_sizes, int n_in,
                              void* d_out, int out_size)
{
    const float* mixture_w = (const float*)d_in[0];  // [B, N, K]
    const float* est_mask  = (const float*)d_in[1];  // [B, N, K]
    const float* W         = (const float*)d_in[2];  // [L, N]
    float* out = (float*)d_out;                       // [B, T]

    cudaMemsetAsync(out, 0, (size_t)out_size * sizeof(float), 0);

    dim3 grid((DEC_K + TPB * KPT - 1) / (TPB * KPT), DEC_B, NSPLIT);  // (63, 4, 4)
    decoder_kernel<<<grid, TPB>>>(mixture_w, est_mask, W, out);
}